// round 14
// baseline (speedup 1.0000x reference)
#include <cuda_runtime.h>
#include <cuda_bf16.h>
#include <cstdint>

#define S_LEN 128
#define T_LEN 128
#define BATCH 16
#define VOCAB 32000

// ---------------- static scratch ----------------
__device__ float g_xproj[2048 * 4096];   // x@Wih^T + b (per stage)
__device__ float g_encC[16384];          // encoder c [dir][b][512]
__device__ float g_dc0[16384], g_dc1[16384]; // decoder c per layer
// bf16 hidden-state ping-pongs (hi/lo pairs)
__device__ __nv_bfloat16 g_ehbA[16384], g_elbA[16384];  // encoder [dir][b][512]
__device__ __nv_bfloat16 g_ehbB[16384], g_elbB[16384];
__device__ __nv_bfloat16 g_dhbA[16384], g_dlbA[16384];  // decoder L0 [b][1024]
__device__ __nv_bfloat16 g_dhbB[16384], g_dlbB[16384];
__device__ __nv_bfloat16 g_dhbC[16384], g_dlbC[16384];  // decoder L1
__device__ __nv_bfloat16 g_dhbD[16384], g_dlbD[16384];
// bf16-split buffers
__device__ __nv_bfloat16 g_Ah[2048 * 1024];   // activations hi (GEMM A)
__device__ __nv_bfloat16 g_Al[2048 * 1024];   // activations lo
__device__ __nv_bfloat16 g_Wh[32768 * 1024];  // Wih / fc_W hi
__device__ __nv_bfloat16 g_Wl[32768 * 1024];
__device__ __nv_bfloat16 g_WrH[4096 * 1024];  // Whh hi (per layer)
__device__ __nv_bfloat16 g_WrL[4096 * 1024];
// grid barrier state
__device__ unsigned g_barc = 0;
__device__ unsigned g_barg = 0;

// ---------------- grid-wide barrier (all blocks co-resident) ----------------
__device__ __forceinline__ void grid_barrier() {
    __threadfence();
    __syncthreads();
    if (threadIdx.x == 0) {
        volatile unsigned* vg = &g_barg;
        const unsigned gen = *vg;
        if (atomicAdd(&g_barc, 1u) == gridDim.x - 1u) {
            g_barc = 0u;
            __threadfence();
            atomicAdd((unsigned*)&g_barg, 1u);
        } else {
            while (*vg == gen) { }
        }
    }
    __syncthreads();
}

// ---------------- embedding gathers -> bf16 hi/lo ----------------
__device__ __forceinline__ void split4_store(__nv_bfloat16* h, __nv_bfloat16* l,
                                             size_t off, float4 v) {
    __nv_bfloat162 h0, h1, l0, l1;
    h0.x = __float2bfloat16(v.x); h0.y = __float2bfloat16(v.y);
    h1.x = __float2bfloat16(v.z); h1.y = __float2bfloat16(v.w);
    l0.x = __float2bfloat16(v.x - __bfloat162float(h0.x));
    l0.y = __float2bfloat16(v.y - __bfloat162float(h0.y));
    l1.x = __float2bfloat16(v.z - __bfloat162float(h1.x));
    l1.y = __float2bfloat16(v.w - __bfloat162float(h1.y));
    *(__nv_bfloat162*)(h + off) = h0; *(__nv_bfloat162*)(h + off + 2) = h1;
    *(__nv_bfloat162*)(l + off) = l0; *(__nv_bfloat162*)(l + off + 2) = l1;
}

__global__ void enc_embed_kernel(const float* __restrict__ emb,
                                 const int* __restrict__ src,
                                 __nv_bfloat16* __restrict__ xh,
                                 __nv_bfloat16* __restrict__ xl) {
    int r = blockIdx.x, t = r >> 4, b = r & 15;
    int tok = src[b * S_LEN + t];
    float4 v = ((const float4*)(emb + (size_t)tok * 1024))[threadIdx.x];
    split4_store(xh, xl, (size_t)r * 1024 + threadIdx.x * 4, v);
}
__global__ void dec_embed_kernel(const float* __restrict__ emb,
                                 const int* __restrict__ tgt,
                                 __nv_bfloat16* __restrict__ xh,
                                 __nv_bfloat16* __restrict__ xl) {
    int r = blockIdx.x, s = r >> 4, b = r & 15;
    int tok = (s == 0) ? 1 : tgt[b * T_LEN + s];
    float4 v = ((const float4*)(emb + (size_t)tok * 1024))[threadIdx.x];
    split4_store(xh, xl, (size_t)r * 1024 + threadIdx.x * 4, v);
}

// ---------------- fp32 -> (hi, lo) bf16 split (weights) ----------------
__global__ void split_kernel(const float2* __restrict__ s,
                             __nv_bfloat162* __restrict__ h,
                             __nv_bfloat162* __restrict__ l, int n2) {
    int i = blockIdx.x * 256 + threadIdx.x;
    if (i < n2) {
        float2 v = s[i];
        __nv_bfloat16 hx = __float2bfloat16(v.x);
        __nv_bfloat16 hy = __float2bfloat16(v.y);
        __nv_bfloat162 hh; hh.x = hx; hh.y = hy;
        __nv_bfloat162 ll;
        ll.x = __float2bfloat16(v.x - __bfloat162float(hx));
        ll.y = __float2bfloat16(v.y - __bfloat162float(hy));
        h[i] = hh;
        l[i] = ll;
    }
}

// ---------------- MMA helpers ----------------
#define LDSM4(d0,d1,d2,d3,addr) \
    asm volatile("ldmatrix.sync.aligned.m8n8.x4.shared.b16 {%0,%1,%2,%3}, [%4];" \
                 : "=r"(d0),"=r"(d1),"=r"(d2),"=r"(d3) : "r"(addr))
#define LDSM2(d0,d1,addr) \
    asm volatile("ldmatrix.sync.aligned.m8n8.x2.shared.b16 {%0,%1}, [%2];" \
                 : "=r"(d0),"=r"(d1) : "r"(addr))
#define MMA16816(c0,c1,c2,c3,a0,a1,a2,a3,b0,b1) \
    asm volatile("mma.sync.aligned.m16n8k16.row.col.f32.bf16.bf16.f32 " \
                 "{%0,%1,%2,%3},{%4,%5,%6,%7},{%8,%9},{%0,%1,%2,%3};" \
                 : "+f"(c0),"+f"(c1),"+f"(c2),"+f"(c3) \
                 : "r"(a0),"r"(a1),"r"(a2),"r"(a3),"r"(b0),"r"(b1))
#define CP16(dst, src) \
    asm volatile("cp.async.cg.shared.global [%0], [%1], 16;" \
                 :: "r"(dst), "l"(src) : "memory")
#define CP_COMMIT() asm volatile("cp.async.commit_group;" ::: "memory")
#define CP_WAIT1()  asm volatile("cp.async.wait_group 1;" ::: "memory")
#define CP_WAIT0()  asm volatile("cp.async.wait_group 0;" ::: "memory")

// ---------------- persistent LSTM chain on tensor cores ----------------
// 512 threads / 16 warps. Block owns 8 units -> N=32 gate rows (ng = gate).
// Warp = K-slice of U/16. A (h) from smem via ldmatrix (bf16 hi/lo), B (Whh)
// from L2. Partials reduced via padded smem; 128-thread gate epilogue.
template <int U, int NDIR>
__global__ void __launch_bounds__(512, 1)
lstm_chain_mma(const __nv_bfloat16* __restrict__ WH,
               const __nv_bfloat16* __restrict__ WL,
               __nv_bfloat16* hbA, __nv_bfloat16* lbA,
               __nv_bfloat16* hbB, __nv_bfloat16* lbB,
               float* __restrict__ c,
               const float* __restrict__ xpbase,   // [nsteps][B][4096]
               __nv_bfloat16* ybh, __nv_bfloat16* ybl,  // optional [nsteps][B][1024]
               int nsteps) {
    extern __shared__ char smraw[];
    __nv_bfloat16* hbs = (__nv_bfloat16*)smraw;        // [16][U+8]
    __nv_bfloat16* lbs = hbs + 16 * (U + 8);
    float* zbuf = (float*)(lbs + 16 * (U + 8));        // [16][16][40]

    const int tid = threadIdx.x, warp = tid >> 5, lane = tid & 31;
    const int dir = (NDIR == 2) ? (blockIdx.x >> 6) : 0;
    const int u0 = ((NDIR == 2) ? (blockIdx.x & 63) : blockIdx.x) * 8;
    const __nv_bfloat16* WHd = WH + (size_t)dir * 4 * U * U;
    const __nv_bfloat16* WLd = WL + (size_t)dir * 4 * U * U;

    const uint32_t hb_sb = (uint32_t)__cvta_generic_to_shared(hbs);
    const uint32_t lb_sb = (uint32_t)__cvta_generic_to_shared(lbs);

    const int eb = tid >> 3, eu = tid & 7;   // epilogue (batch, unit-offset), tid<128
    const int uu = u0 + eu;
    const size_t cidx = (size_t)dir * BATCH * U + (size_t)eb * U + uu;
    float cr = (tid < 128) ? c[cidx] : 0.f;

    constexpr int KT = U / 256;              // k-tiles (of 16) per warp
    const int kbase = warp * (U / 16);
    const uint32_t aoff = (uint32_t)(((lane & 15) * (U + 8) + ((lane >> 4) << 3)) * 2);
    const int brow = (lane >> 2);            // 0..7 within unit group
    const int bk = (lane & 3) << 1;

    for (int j = 0; j < nsteps; ++j) {
        const __nv_bfloat16* hin_h = (j & 1) ? hbB : hbA;
        const __nv_bfloat16* hin_l = (j & 1) ? lbB : lbA;
        __nv_bfloat16* hout_h = (j & 1) ? hbA : hbB;
        __nv_bfloat16* hout_l = (j & 1) ? lbA : lbB;

        // xp prefetch (epilogue threads only)
        float xpi = 0.f, xpf = 0.f, xpg = 0.f, xpo = 0.f;
        size_t yoff = 0;
        if (tid < 128) {
            const float* xp;
            if (NDIR == 2 && dir == 1) {
                const int jr = nsteps - 1 - j;
                xp = xpbase + (size_t)jr * 65536 + 2048 + (size_t)eb * 4096;
                yoff = (size_t)jr * 16384 + (size_t)eb * 1024 + 512 + uu;
            } else {
                xp = xpbase + (size_t)j * 65536 + (size_t)eb * 4096;
                yoff = (size_t)j * 16384 + (size_t)eb * 1024 + uu;
            }
            xpi = __ldg(xp + 0 * U + uu);
            xpf = __ldg(xp + 1 * U + uu);
            xpg = __ldg(xp + 2 * U + uu);
            xpo = __ldg(xp + 3 * U + uu);
        }

        // load h (bf16 hi/lo) into padded smem, L1-bypassed
        {
            const uint4* s4h = (const uint4*)(hin_h + (size_t)dir * 16 * U);
            const uint4* s4l = (const uint4*)(hin_l + (size_t)dir * 16 * U);
            constexpr int C8 = U / 8;
            for (int i = tid; i < 16 * C8; i += 512) {
                const int row = i / C8, c8 = i - row * C8;
                *(uint4*)(hbs + row * (U + 8) + c8 * 8) = __ldcg(s4h + i);
                *(uint4*)(lbs + row * (U + 8) + c8 * 8) = __ldcg(s4l + i);
            }
        }
        __syncthreads();

        float acc[4][4];
#pragma unroll
        for (int g = 0; g < 4; ++g)
#pragma unroll
            for (int q = 0; q < 4; ++q) acc[g][q] = 0.f;

#pragma unroll
        for (int t = 0; t < KT; ++t) {
            const int kk = kbase + t * 16;
            uint32_t ah0, ah1, ah2, ah3, al0, al1, al2, al3;
            LDSM4(ah0, ah1, ah2, ah3, hb_sb + aoff + kk * 2);
            LDSM4(al0, al1, al2, al3, lb_sb + aoff + kk * 2);
            // batch all B loads for MLP
            uint32_t bh[4][2], bl[4][2];
#pragma unroll
            for (int g = 0; g < 4; ++g) {
                const size_t ro = (size_t)(g * U + u0 + brow) * U + kk + bk;
                bh[g][0] = __ldg((const unsigned int*)(WHd + ro));
                bh[g][1] = __ldg((const unsigned int*)(WHd + ro + 8));
                bl[g][0] = __ldg((const unsigned int*)(WLd + ro));
                bl[g][1] = __ldg((const unsigned int*)(WLd + ro + 8));
            }
#pragma unroll
            for (int g = 0; g < 4; ++g) {
                MMA16816(acc[g][0], acc[g][1], acc[g][2], acc[g][3],
                         ah0, ah1, ah2, ah3, bh[g][0], bh[g][1]);
                MMA16816(acc[g][0], acc[g][1], acc[g][2], acc[g][3],
                         ah0, ah1, ah2, ah3, bl[g][0], bl[g][1]);
                MMA16816(acc[g][0], acc[g][1], acc[g][2], acc[g][3],
                         al0, al1, al2, al3, bh[g][0], bh[g][1]);
            }
        }
        // store partial z: zbuf[warp][b][n], row stride 40 (bank-spread)
        {
            const int r0 = lane >> 2;
#pragma unroll
            for (int g = 0; g < 4; ++g) {
                const int n = g * 8 + bk;
                float2 v01; v01.x = acc[g][0]; v01.y = acc[g][1];
                float2 v23; v23.x = acc[g][2]; v23.y = acc[g][3];
                *(float2*)(zbuf + (warp * 16 + r0) * 40 + n) = v01;
                *(float2*)(zbuf + (warp * 16 + r0 + 8) * 40 + n) = v23;
            }
        }
        __syncthreads();

        if (tid < 128) {
            float z0 = xpi, z1 = xpf, z2 = xpg, z3 = xpo;
#pragma unroll
            for (int s = 0; s < 16; ++s) {
                const float* zr = zbuf + (s * 16 + eb) * 40;
                z0 += zr[0 * 8 + eu];
                z1 += zr[1 * 8 + eu];
                z2 += zr[2 * 8 + eu];
                z3 += zr[3 * 8 + eu];
            }
            const float ig = 1.f / (1.f + __expf(-z0));
            const float fg = 1.f / (1.f + __expf(-z1));
            const float gg = tanhf(z2);
            const float og = 1.f / (1.f + __expf(-z3));
            const float cn = fg * cr + ig * gg;
            cr = cn;
            const float hn = og * tanhf(cn);
            const __nv_bfloat16 hh = __float2bfloat16(hn);
            const __nv_bfloat16 hl = __float2bfloat16(hn - __bfloat162float(hh));
            const size_t ho = (size_t)dir * 16 * U + (size_t)eb * U + uu;
            hout_h[ho] = hh; hout_l[ho] = hl;
            if (ybh) { ybh[yoff] = hh; ybl[yoff] = hl; }
        }
        if (j + 1 < nsteps) grid_barrier();
    }
    if (tid < 128) c[cidx] = cr;
}

// ---------------- bf16-split NT GEMM (R11 structure, 152us) ----------------
#define SPAD 40
#define TILE_B (128 * SPAD * 2)
#define STAGE_B (4 * TILE_B)
#define GEMM_SMEM (2 * STAGE_B)

__device__ __forceinline__ void store_c(float* __restrict__ C, int m, int cc,
                                        float v0, float v1, int M, int N, int fcmode) {
    if (m >= M) return;
    float2 v; v.x = v0; v.y = v1;
    if (fcmode) {
        const int b = m & 15, t = (m >> 4) + 1;
        *(float2*)&C[(size_t)b * T_LEN * VOCAB + (size_t)t * VOCAB + cc] = v;
    } else {
        *(float2*)&C[(size_t)m * N + cc] = v;
    }
}

__global__ void __launch_bounds__(256, 2)
gemm_bf16x3_kernel(const __nv_bfloat16* __restrict__ Ah, const __nv_bfloat16* __restrict__ Al,
                   const __nv_bfloat16* __restrict__ Bh, const __nv_bfloat16* __restrict__ Bl,
                   const float* __restrict__ bias, float* __restrict__ C,
                   int M, int N, int K, int fcmode) {
    extern __shared__ __nv_bfloat16 sm[];
    const int tid = threadIdx.x, warp = tid >> 5, lane = tid & 31;
    const int wm = warp >> 2, wn = warp & 3;
    const int m0 = blockIdx.y * 128, n0 = blockIdx.x * 128;
    const int lrow = tid >> 2;
    const int lcol = (tid & 3) << 3;
    const uint32_t smbase = (uint32_t)__cvta_generic_to_shared(sm);

    float acc[4][4][4];
#pragma unroll
    for (int i = 0; i < 4; ++i)
#pragma unroll
        for (int j = 0; j < 4; ++j)
#pragma unroll
            for (int q = 0; q < 4; ++q) acc[i][j][q] = 0.f;

    const int a_row = wm * 64 + (lane & 15);
    const int a_csel = (lane >> 4) << 3;
    const int b_row = wn * 32 + (lane & 7);
    const int b_csel = lane & 8;
    const int NT = K >> 5;

    auto issue_stage = [&](int kt, int s) {
        const int kc = kt << 5;
        const uint32_t stg = smbase + (uint32_t)(s * STAGE_B);
#pragma unroll
        for (int i = 0; i < 2; ++i) {
            const int r = lrow + i * 64;
            const size_t ga = (size_t)(m0 + r) * K + kc + lcol;
            const size_t gb = (size_t)(n0 + r) * K + kc + lcol;
            const uint32_t so = (uint32_t)(r * SPAD + lcol) * 2;
            CP16(stg + 0 * TILE_B + so, Ah + ga);
            CP16(stg + 1 * TILE_B + so, Al + ga);
            CP16(stg + 2 * TILE_B + so, Bh + gb);
            CP16(stg + 3 * TILE_B + so, Bl + gb);
        }
    };

    issue_stage(0, 0);
    CP_COMMIT();

    for (int kt = 0; kt < NT; ++kt) {
        const int s = kt & 1;
        if (kt + 1 < NT) {
            issue_stage(kt + 1, s ^ 1);
            CP_COMMIT();
            CP_WAIT1();
        } else {
            CP_WAIT0();
        }
        __syncthreads();
        const uint32_t stg = smbase + (uint32_t)(s * STAGE_B);
#pragma unroll
        for (int h = 0; h < 2; ++h) {
            const int kk = h << 4;
            uint32_t afh[4][4], afl[4][4], bfh[4][2], bfl[4][2];
#pragma unroll
            for (int mi = 0; mi < 4; ++mi) {
                const uint32_t off = (uint32_t)(((a_row + mi * 16) * SPAD + kk + a_csel) * 2);
                LDSM4(afh[mi][0], afh[mi][1], afh[mi][2], afh[mi][3], stg + 0 * TILE_B + off);
                LDSM4(afl[mi][0], afl[mi][1], afl[mi][2], afl[mi][3], stg + 1 * TILE_B + off);
            }
#pragma unroll
            for (int ni = 0; ni < 4; ++ni) {
                const uint32_t off = (uint32_t)(((b_row + ni * 8) * SPAD + kk + b_csel) * 2);
                LDSM2(bfh[ni][0], bfh[ni][1], stg + 2 * TILE_B + off);
                LDSM2(bfl[ni][0], bfl[ni][1], stg + 3 * TILE_B + off);
            }
#pragma unroll
            for (int mi = 0; mi < 4; ++mi)
#pragma unroll
                for (int ni = 0; ni < 4; ++ni) {
                    float* c4 = acc[mi][ni];
                    MMA16816(c4[0], c4[1], c4[2], c4[3],
                             afh[mi][0], afh[mi][1], afh[mi][2], afh[mi][3],
                             bfh[ni][0], bfh[ni][1]);
                    MMA16816(c4[0], c4[1], c4[2], c4[3],
                             afh[mi][0], afh[mi][1], afh[mi][2], afh[mi][3],
                             bfl[ni][0], bfl[ni][1]);
                    MMA16816(c4[0], c4[1], c4[2], c4[3],
                             afl[mi][0], afl[mi][1], afl[mi][2], afl[mi][3],
                             bfh[ni][0], bfh[ni][1]);
                }
        }
        __syncthreads();
    }

    const int g = lane >> 2, tc = lane & 3;
#pragma unroll
    for (int mi = 0; mi < 4; ++mi) {
#pragma unroll
        for (int ni = 0; ni < 4; ++ni) {
            const int r0 = m0 + wm * 64 + mi * 16 + g;
            const int cc = n0 + wn * 32 + ni * 8 + tc * 2;
            const float bb0 = bias[cc], bb1 = bias[cc + 1];
            store_c(C, r0,     cc, acc[mi][ni][0] + bb0, acc[mi][ni][1] + bb1, M, N, fcmode);
            store_c(C, r0 + 8, cc, acc[mi][ni][2] + bb0, acc[mi][ni][3] + bb1, M, N, fcmode);
        }
    }
}

// encoder [dir][b][512] (bf16 + c fp32) -> decoder [b][1024]
__global__ void concat_hc_kernel(const __nv_bfloat16* __restrict__ hsrc,
                                 const __nv_bfloat16* __restrict__ lsrc,
                                 const float* __restrict__ csrc,
                                 __nv_bfloat16* __restrict__ hdst,
                                 __nv_bfloat16* __restrict__ ldst,
                                 float* __restrict__ cdst) {
    const int idx = blockIdx.x * 256 + threadIdx.x;
    const int b = idx >> 10, col = idx & 1023;
    const int dir = col >> 9, u = col & 511;
    const int s = dir * 8192 + b * 512 + u;
    hdst[idx] = hsrc[s];
    ldst[idx] = lsrc[s];
    cdst[idx] = csrc[s];
}

__global__ void zero_t0_kernel(float* __restrict__ out) {
    const int idx = blockIdx.x * 256 + threadIdx.x;
    if (idx < 16 * VOCAB) {
        const int b = idx / VOCAB, v = idx - b * VOCAB;
        out[(size_t)b * T_LEN * VOCAB + v] = 0.f;
    }
}

// ---------------- driver ----------------
extern "C" void kernel_launch(void* const* d_in, const int* in_sizes, int n_in,
                              void* d_out, int out_size) {
    (void)in_sizes; (void)n_in; (void)out_size;
    const int*   src       = (const int*)d_in[0];
    const int*   tgt       = (const int*)d_in[1];
    const float* enc_embed = (const float*)d_in[3];
    const float* enc_Wih   = (const float*)d_in[4];
    const float* enc_Whh   = (const float*)d_in[5];
    const float* enc_b     = (const float*)d_in[6];
    const float* dec_embed = (const float*)d_in[7];
    const float* dec_Wih   = (const float*)d_in[8];
    const float* dec_Whh   = (const float*)d_in[9];
    const float* dec_b     = (const float*)d_in[10];
    const float* fc_W      = (const float*)d_in[11];
    const float* fc_b      = (const float*)d_in[12];
    float* out = (float*)d_out;

    float *xp, *eC, *c0, *c1;
    __nv_bfloat16 *Ah, *Al, *Wh, *Wl, *WrH, *WrL;
    __nv_bfloat16 *ehbA,*elbA,*ehbB,*elbB;
    __nv_bfloat16 *dhbA,*dlbA,*dhbB,*dlbB,*dhbC,*dlbC,*dhbD,*dlbD;
    cudaGetSymbolAddress((void**)&xp, g_xproj);
    cudaGetSymbolAddress((void**)&eC, g_encC);
    cudaGetSymbolAddress((void**)&c0, g_dc0);
    cudaGetSymbolAddress((void**)&c1, g_dc1);
    cudaGetSymbolAddress((void**)&Ah, g_Ah);
    cudaGetSymbolAddress((void**)&Al, g_Al);
    cudaGetSymbolAddress((void**)&Wh, g_Wh);
    cudaGetSymbolAddress((void**)&Wl, g_Wl);
    cudaGetSymbolAddress((void**)&WrH, g_WrH);
    cudaGetSymbolAddress((void**)&WrL, g_WrL);
    cudaGetSymbolAddress((void**)&ehbA, g_ehbA);
    cudaGetSymbolAddress((void**)&elbA, g_elbA);
    cudaGetSymbolAddress((void**)&ehbB, g_ehbB);
    cudaGetSymbolAddress((void**)&elbB, g_elbB);
    cudaGetSymbolAddress((void**)&dhbA, g_dhbA);
    cudaGetSymbolAddress((void**)&dlbA, g_dlbA);
    cudaGetSymbolAddress((void**)&dhbB, g_dhbB);
    cudaGetSymbolAddress((void**)&dlbB, g_dlbB);
    cudaGetSymbolAddress((void**)&dhbC, g_dhbC);
    cudaGetSymbolAddress((void**)&dlbC, g_dlbC);
    cudaGetSymbolAddress((void**)&dhbD, g_dhbD);
    cudaGetSymbolAddress((void**)&dlbD, g_dlbD);

    const int ENC_SMEM = 2 * 16 * (512 + 8) * 2 + 16 * 16 * 40 * 4;   // 74240
    const int DEC_SMEM = 2 * 16 * (1024 + 8) * 2 + 16 * 16 * 40 * 4;  // 107008
    cudaFuncSetAttribute(lstm_chain_mma<512, 2>,
                         cudaFuncAttributeMaxDynamicSharedMemorySize, ENC_SMEM);
    cudaFuncSetAttribute(lstm_chain_mma<1024, 1>,
                         cudaFuncAttributeMaxDynamicSharedMemorySize, DEC_SMEM);
    cudaFuncSetAttribute(gemm_bf16x3_kernel,
                         cudaFuncAttributeMaxDynamicSharedMemorySize, GEMM_SMEM);

    auto splitN = [](const float* s, __nv_bfloat16* h, __nv_bfloat16* l, int n) {
        int n2 = n >> 1;
        split_kernel<<<(n2 + 255) / 256, 256>>>((const float2*)s,
                                                (__nv_bfloat162*)h, (__nv_bfloat162*)l, n2);
    };

    // ===== Encoder =====
    enc_embed_kernel<<<2048, 256>>>(enc_embed, src, Ah, Al);
    for (int l = 0; l < 2; ++l) {
        cudaMemsetAsync(ehbA, 0, 16384 * sizeof(__nv_bfloat16));
        cudaMemsetAsync(elbA, 0, 16384 * sizeof(__nv_bfloat16));
        cudaMemsetAsync(eC, 0, 16384 * sizeof(float));
        splitN(enc_Wih + (size_t)l * 4096 * 1024, Wh, Wl, 4096 * 1024);
        gemm_bf16x3_kernel<<<dim3(32, 16), 256, GEMM_SMEM>>>(
            Ah, Al, Wh, Wl, enc_b + l * 4096, xp, 2048, 4096, 1024, 0);
        splitN(enc_Whh + (size_t)l * 2 * 2048 * 512, WrH, WrL, 2 * 2048 * 512);
        lstm_chain_mma<512, 2><<<128, 512, ENC_SMEM>>>(
            WrH, WrL, ehbA, elbA, ehbB, elbB, eC, xp,
            (l == 0) ? Ah : nullptr, (l == 0) ? Al : nullptr, 128);
        // 128 steps -> final h in A buffers
        __nv_bfloat16* hd = (l == 0) ? dhbA : dhbC;
        __nv_bfloat16* ld = (l == 0) ? dlbA : dlbC;
        float* cd = (l == 0) ? c0 : c1;
        concat_hc_kernel<<<64, 256>>>(ehbA, elbA, eC, hd, ld, cd);
    }

    // ===== Decoder =====
    dec_embed_kernel<<<2032, 256>>>(dec_embed, tgt, Ah, Al);
    // layer 0
    splitN(dec_Wih, Wh, Wl, 4096 * 1024);
    gemm_bf16x3_kernel<<<dim3(32, 16), 256, GEMM_SMEM>>>(
        Ah, Al, Wh, Wl, dec_b, xp, 2032, 4096, 1024, 0);
    splitN(dec_Whh, WrH, WrL, 4096 * 1024);
    lstm_chain_mma<1024, 1><<<128, 512, DEC_SMEM>>>(
        WrH, WrL, dhbA, dlbA, dhbB, dlbB, c0, xp, Ah, Al, 127);   // h0seq -> Ah/Al
    // layer 1
    splitN(dec_Wih + (size_t)4096 * 1024, Wh, Wl, 4096 * 1024);
    gemm_bf16x3_kernel<<<dim3(32, 16), 256, GEMM_SMEM>>>(
        Ah, Al, Wh, Wl, dec_b + 4096, xp, 2032, 4096, 1024, 0);
    splitN(dec_Whh + (size_t)4096 * 1024, WrH, WrL, 4096 * 1024);
    lstm_chain_mma<1024, 1><<<128, 512, DEC_SMEM>>>(
        WrH, WrL, dhbC, dlbC, dhbD, dlbD, c1, xp, Ah, Al, 127);   // h1seq -> Ah/Al

    // ===== Output =====
    zero_t0_kernel<<<2000, 256>>>(out);
    splitN(fc_W, Wh, Wl, 32000 * 1024);
    gemm_bf16x3_kernel<<<dim3(250, 16), 256, GEMM_SMEM>>>(
        Ah, Al, Wh, Wl, fc_b, out, 2032, VOCAB, 1024, 1);
}

// round 15
// speedup vs baseline: 1.3852x; 1.3852x over previous
#include <cuda_runtime.h>
#include <cuda_bf16.h>
#include <cstdint>

#define S_LEN 128
#define T_LEN 128
#define BATCH 16
#define VOCAB 32000

// ---------------- static scratch ----------------
__device__ float g_xproj[2048 * 4096];   // x@Wih^T + b (per stage)
__device__ float g_encC[16384];          // encoder c [dir][b][512]
__device__ float g_dc0[16384], g_dc1[16384]; // decoder c per layer
// bf16 hidden-state ping-pongs (hi/lo pairs)
__device__ __nv_bfloat16 g_ehbA[16384], g_elbA[16384];  // encoder [dir][b][512]
__device__ __nv_bfloat16 g_ehbB[16384], g_elbB[16384];
__device__ __nv_bfloat16 g_dhbA[16384], g_dlbA[16384];  // decoder L0 [b][1024]
__device__ __nv_bfloat16 g_dhbB[16384], g_dlbB[16384];
__device__ __nv_bfloat16 g_dhbC[16384], g_dlbC[16384];  // decoder L1
__device__ __nv_bfloat16 g_dhbD[16384], g_dlbD[16384];
// bf16-split buffers
__device__ __nv_bfloat16 g_Ah[2048 * 1024];   // activations hi (GEMM A)
__device__ __nv_bfloat16 g_Al[2048 * 1024];   // activations lo
__device__ __nv_bfloat16 g_Wh[32768 * 1024];  // Wih / fc_W hi
__device__ __nv_bfloat16 g_Wl[32768 * 1024];
__device__ __nv_bfloat16 g_WrH[4096 * 1024];  // Whh hi (per layer)
__device__ __nv_bfloat16 g_WrL[4096 * 1024];
// grid barrier state
__device__ unsigned g_barc = 0;
__device__ unsigned g_barg = 0;

// ---------------- grid-wide barrier (all blocks co-resident) ----------------
__device__ __forceinline__ void grid_barrier() {
    __threadfence();
    __syncthreads();
    if (threadIdx.x == 0) {
        volatile unsigned* vg = &g_barg;
        const unsigned gen = *vg;
        if (atomicAdd(&g_barc, 1u) == gridDim.x - 1u) {
            g_barc = 0u;
            __threadfence();
            atomicAdd((unsigned*)&g_barg, 1u);
        } else {
            while (*vg == gen) { }
        }
    }
    __syncthreads();
}

// ---------------- embedding gathers -> bf16 hi/lo ----------------
__device__ __forceinline__ void split4_store(__nv_bfloat16* h, __nv_bfloat16* l,
                                             size_t off, float4 v) {
    __nv_bfloat162 h0, h1, l0, l1;
    h0.x = __float2bfloat16(v.x); h0.y = __float2bfloat16(v.y);
    h1.x = __float2bfloat16(v.z); h1.y = __float2bfloat16(v.w);
    l0.x = __float2bfloat16(v.x - __bfloat162float(h0.x));
    l0.y = __float2bfloat16(v.y - __bfloat162float(h0.y));
    l1.x = __float2bfloat16(v.z - __bfloat162float(h1.x));
    l1.y = __float2bfloat16(v.w - __bfloat162float(h1.y));
    *(__nv_bfloat162*)(h + off) = h0; *(__nv_bfloat162*)(h + off + 2) = h1;
    *(__nv_bfloat162*)(l + off) = l0; *(__nv_bfloat162*)(l + off + 2) = l1;
}

__global__ void enc_embed_kernel(const float* __restrict__ emb,
                                 const int* __restrict__ src,
                                 __nv_bfloat16* __restrict__ xh,
                                 __nv_bfloat16* __restrict__ xl) {
    int r = blockIdx.x, t = r >> 4, b = r & 15;
    int tok = src[b * S_LEN + t];
    float4 v = ((const float4*)(emb + (size_t)tok * 1024))[threadIdx.x];
    split4_store(xh, xl, (size_t)r * 1024 + threadIdx.x * 4, v);
}
__global__ void dec_embed_kernel(const float* __restrict__ emb,
                                 const int* __restrict__ tgt,
                                 __nv_bfloat16* __restrict__ xh,
                                 __nv_bfloat16* __restrict__ xl) {
    int r = blockIdx.x, s = r >> 4, b = r & 15;
    int tok = (s == 0) ? 1 : tgt[b * T_LEN + s];
    float4 v = ((const float4*)(emb + (size_t)tok * 1024))[threadIdx.x];
    split4_store(xh, xl, (size_t)r * 1024 + threadIdx.x * 4, v);
}

// ---------------- fp32 -> (hi, lo) bf16 split (weights) ----------------
__global__ void split_kernel(const float2* __restrict__ s,
                             __nv_bfloat162* __restrict__ h,
                             __nv_bfloat162* __restrict__ l, int n2) {
    int i = blockIdx.x * 256 + threadIdx.x;
    if (i < n2) {
        float2 v = s[i];
        __nv_bfloat16 hx = __float2bfloat16(v.x);
        __nv_bfloat16 hy = __float2bfloat16(v.y);
        __nv_bfloat162 hh; hh.x = hx; hh.y = hy;
        __nv_bfloat162 ll;
        ll.x = __float2bfloat16(v.x - __bfloat162float(hx));
        ll.y = __float2bfloat16(v.y - __bfloat162float(hy));
        h[i] = hh;
        l[i] = ll;
    }
}

// ---------------- MMA helpers ----------------
#define LDSM4(d0,d1,d2,d3,addr) \
    asm volatile("ldmatrix.sync.aligned.m8n8.x4.shared.b16 {%0,%1,%2,%3}, [%4];" \
                 : "=r"(d0),"=r"(d1),"=r"(d2),"=r"(d3) : "r"(addr))
#define LDSM2(d0,d1,addr) \
    asm volatile("ldmatrix.sync.aligned.m8n8.x2.shared.b16 {%0,%1}, [%2];" \
                 : "=r"(d0),"=r"(d1) : "r"(addr))
#define MMA16816(c0,c1,c2,c3,a0,a1,a2,a3,b0,b1) \
    asm volatile("mma.sync.aligned.m16n8k16.row.col.f32.bf16.bf16.f32 " \
                 "{%0,%1,%2,%3},{%4,%5,%6,%7},{%8,%9},{%0,%1,%2,%3};" \
                 : "+f"(c0),"+f"(c1),"+f"(c2),"+f"(c3) \
                 : "r"(a0),"r"(a1),"r"(a2),"r"(a3),"r"(b0),"r"(b1))
#define CP16(dst, src) \
    asm volatile("cp.async.cg.shared.global [%0], [%1], 16;" \
                 :: "r"(dst), "l"(src) : "memory")
#define CP_COMMIT() asm volatile("cp.async.commit_group;" ::: "memory")
#define CP_WAIT1()  asm volatile("cp.async.wait_group 1;" ::: "memory")
#define CP_WAIT0()  asm volatile("cp.async.wait_group 0;" ::: "memory")

// ---------------- persistent LSTM chain on tensor cores ----------------
// 512 threads / 16 warps. Block owns 8 units -> N=32 gate rows.
// Warp = K-slice of U/16. Whh fragments hoisted into REGISTERS before the
// step loop (loop-invariant). Per step: h via ldmatrix, 12 reg-resident MMAs,
// smem partial reduce, 128-thread gate epilogue.
template <int U, int NDIR>
__global__ void __launch_bounds__(512, 1)
lstm_chain_mma(const __nv_bfloat16* __restrict__ WH,
               const __nv_bfloat16* __restrict__ WL,
               __nv_bfloat16* hbA, __nv_bfloat16* lbA,
               __nv_bfloat16* hbB, __nv_bfloat16* lbB,
               float* __restrict__ c,
               const float* __restrict__ xpbase,   // [nsteps][B][4096]
               __nv_bfloat16* ybh, __nv_bfloat16* ybl,  // optional [nsteps][B][1024]
               int nsteps) {
    extern __shared__ char smraw[];
    __nv_bfloat16* hbs = (__nv_bfloat16*)smraw;        // [16][U+8]
    __nv_bfloat16* lbs = hbs + 16 * (U + 8);
    float* zbuf = (float*)(lbs + 16 * (U + 8));        // [16][16][40]

    const int tid = threadIdx.x, warp = tid >> 5, lane = tid & 31;
    const int dir = (NDIR == 2) ? (blockIdx.x >> 6) : 0;
    const int u0 = ((NDIR == 2) ? (blockIdx.x & 63) : blockIdx.x) * 8;
    const __nv_bfloat16* WHd = WH + (size_t)dir * 4 * U * U;
    const __nv_bfloat16* WLd = WL + (size_t)dir * 4 * U * U;

    const uint32_t hb_sb = (uint32_t)__cvta_generic_to_shared(hbs);
    const uint32_t lb_sb = (uint32_t)__cvta_generic_to_shared(lbs);

    const int eb = tid >> 3, eu = tid & 7;   // epilogue (batch, unit-offset), tid<128
    const int uu = u0 + eu;
    const size_t cidx = (size_t)dir * BATCH * U + (size_t)eb * U + uu;
    float cr = (tid < 128) ? c[cidx] : 0.f;

    constexpr int KT = U / 256;              // k-tiles (of 16) per warp
    const int kbase = warp * (U / 16);
    const uint32_t aoff = (uint32_t)(((lane & 15) * (U + 8) + ((lane >> 4) << 3)) * 2);
    const int brow = (lane >> 2);
    const int bk = (lane & 3) << 1;

    // ---- hoist Whh fragments into registers (loop-invariant B operands) ----
    uint32_t Bh[KT][4][2], Bl[KT][4][2];
#pragma unroll
    for (int t = 0; t < KT; ++t) {
        const int kk = kbase + t * 16;
#pragma unroll
        for (int g = 0; g < 4; ++g) {
            const size_t ro = (size_t)(g * U + u0 + brow) * U + kk + bk;
            Bh[t][g][0] = *(const unsigned int*)(WHd + ro);
            Bh[t][g][1] = *(const unsigned int*)(WHd + ro + 8);
            Bl[t][g][0] = *(const unsigned int*)(WLd + ro);
            Bl[t][g][1] = *(const unsigned int*)(WLd + ro + 8);
        }
    }

    for (int j = 0; j < nsteps; ++j) {
        const __nv_bfloat16* hin_h = (j & 1) ? hbB : hbA;
        const __nv_bfloat16* hin_l = (j & 1) ? lbB : lbA;
        __nv_bfloat16* hout_h = (j & 1) ? hbA : hbB;
        __nv_bfloat16* hout_l = (j & 1) ? lbA : lbB;

        // xp prefetch (epilogue threads only)
        float xpi = 0.f, xpf = 0.f, xpg = 0.f, xpo = 0.f;
        size_t yoff = 0;
        if (tid < 128) {
            const float* xp;
            if (NDIR == 2 && dir == 1) {
                const int jr = nsteps - 1 - j;
                xp = xpbase + (size_t)jr * 65536 + 2048 + (size_t)eb * 4096;
                yoff = (size_t)jr * 16384 + (size_t)eb * 1024 + 512 + uu;
            } else {
                xp = xpbase + (size_t)j * 65536 + (size_t)eb * 4096;
                yoff = (size_t)j * 16384 + (size_t)eb * 1024 + uu;
            }
            xpi = __ldg(xp + 0 * U + uu);
            xpf = __ldg(xp + 1 * U + uu);
            xpg = __ldg(xp + 2 * U + uu);
            xpo = __ldg(xp + 3 * U + uu);
        }

        // load h (bf16 hi/lo) into padded smem, L1-bypassed
        {
            const uint4* s4h = (const uint4*)(hin_h + (size_t)dir * 16 * U);
            const uint4* s4l = (const uint4*)(hin_l + (size_t)dir * 16 * U);
            constexpr int C8 = U / 8;
            for (int i = tid; i < 16 * C8; i += 512) {
                const int row = i / C8, c8 = i - row * C8;
                *(uint4*)(hbs + row * (U + 8) + c8 * 8) = __ldcg(s4h + i);
                *(uint4*)(lbs + row * (U + 8) + c8 * 8) = __ldcg(s4l + i);
            }
        }
        __syncthreads();

        float acc[4][4];
#pragma unroll
        for (int g = 0; g < 4; ++g)
#pragma unroll
            for (int q = 0; q < 4; ++q) acc[g][q] = 0.f;

#pragma unroll
        for (int t = 0; t < KT; ++t) {
            const int kk = kbase + t * 16;
            uint32_t ah0, ah1, ah2, ah3, al0, al1, al2, al3;
            LDSM4(ah0, ah1, ah2, ah3, hb_sb + aoff + kk * 2);
            LDSM4(al0, al1, al2, al3, lb_sb + aoff + kk * 2);
#pragma unroll
            for (int g = 0; g < 4; ++g) {
                MMA16816(acc[g][0], acc[g][1], acc[g][2], acc[g][3],
                         ah0, ah1, ah2, ah3, Bh[t][g][0], Bh[t][g][1]);
                MMA16816(acc[g][0], acc[g][1], acc[g][2], acc[g][3],
                         ah0, ah1, ah2, ah3, Bl[t][g][0], Bl[t][g][1]);
                MMA16816(acc[g][0], acc[g][1], acc[g][2], acc[g][3],
                         al0, al1, al2, al3, Bh[t][g][0], Bh[t][g][1]);
            }
        }
        // store partial z: zbuf[warp][b][n], row stride 40 (bank-spread)
        {
            const int r0 = lane >> 2;
#pragma unroll
            for (int g = 0; g < 4; ++g) {
                const int n = g * 8 + bk;
                float2 v01; v01.x = acc[g][0]; v01.y = acc[g][1];
                float2 v23; v23.x = acc[g][2]; v23.y = acc[g][3];
                *(float2*)(zbuf + (warp * 16 + r0) * 40 + n) = v01;
                *(float2*)(zbuf + (warp * 16 + r0 + 8) * 40 + n) = v23;
            }
        }
        __syncthreads();

        if (tid < 128) {
            float z0 = xpi, z1 = xpf, z2 = xpg, z3 = xpo;
#pragma unroll
            for (int s = 0; s < 16; ++s) {
                const float* zr = zbuf + (s * 16 + eb) * 40;
                z0 += zr[0 * 8 + eu];
                z1 += zr[1 * 8 + eu];
                z2 += zr[2 * 8 + eu];
                z3 += zr[3 * 8 + eu];
            }
            const float ig = 1.f / (1.f + __expf(-z0));
            const float fg = 1.f / (1.f + __expf(-z1));
            const float gg = tanhf(z2);
            const float og = 1.f / (1.f + __expf(-z3));
            const float cn = fg * cr + ig * gg;
            cr = cn;
            const float hn = og * tanhf(cn);
            const __nv_bfloat16 hh = __float2bfloat16(hn);
            const __nv_bfloat16 hl = __float2bfloat16(hn - __bfloat162float(hh));
            const size_t ho = (size_t)dir * 16 * U + (size_t)eb * U + uu;
            hout_h[ho] = hh; hout_l[ho] = hl;
            if (ybh) { ybh[yoff] = hh; ybl[yoff] = hl; }
        }
        if (j + 1 < nsteps) grid_barrier();
    }
    if (tid < 128) c[cidx] = cr;
}

// ---------------- bf16-split NT GEMM (R11 structure) ----------------
#define SPAD 40
#define TILE_B (128 * SPAD * 2)
#define STAGE_B (4 * TILE_B)
#define GEMM_SMEM (2 * STAGE_B)

__device__ __forceinline__ void store_c(float* __restrict__ C, int m, int cc,
                                        float v0, float v1, int M, int N, int fcmode) {
    if (m >= M) return;
    float2 v; v.x = v0; v.y = v1;
    if (fcmode) {
        const int b = m & 15, t = (m >> 4) + 1;
        *(float2*)&C[(size_t)b * T_LEN * VOCAB + (size_t)t * VOCAB + cc] = v;
    } else {
        *(float2*)&C[(size_t)m * N + cc] = v;
    }
}

__global__ void __launch_bounds__(256, 2)
gemm_bf16x3_kernel(const __nv_bfloat16* __restrict__ Ah, const __nv_bfloat16* __restrict__ Al,
                   const __nv_bfloat16* __restrict__ Bh, const __nv_bfloat16* __restrict__ Bl,
                   const float* __restrict__ bias, float* __restrict__ C,
                   int M, int N, int K, int fcmode) {
    extern __shared__ __nv_bfloat16 sm[];
    const int tid = threadIdx.x, warp = tid >> 5, lane = tid & 31;
    const int wm = warp >> 2, wn = warp & 3;
    const int m0 = blockIdx.y * 128, n0 = blockIdx.x * 128;
    const int lrow = tid >> 2;
    const int lcol = (tid & 3) << 3;
    const uint32_t smbase = (uint32_t)__cvta_generic_to_shared(sm);

    float acc[4][4][4];
#pragma unroll
    for (int i = 0; i < 4; ++i)
#pragma unroll
        for (int j = 0; j < 4; ++j)
#pragma unroll
            for (int q = 0; q < 4; ++q) acc[i][j][q] = 0.f;

    const int a_row = wm * 64 + (lane & 15);
    const int a_csel = (lane >> 4) << 3;
    const int b_row = wn * 32 + (lane & 7);
    const int b_csel = lane & 8;
    const int NT = K >> 5;

    auto issue_stage = [&](int kt, int s) {
        const int kc = kt << 5;
        const uint32_t stg = smbase + (uint32_t)(s * STAGE_B);
#pragma unroll
        for (int i = 0; i < 2; ++i) {
            const int r = lrow + i * 64;
            const size_t ga = (size_t)(m0 + r) * K + kc + lcol;
            const size_t gb = (size_t)(n0 + r) * K + kc + lcol;
            const uint32_t so = (uint32_t)(r * SPAD + lcol) * 2;
            CP16(stg + 0 * TILE_B + so, Ah + ga);
            CP16(stg + 1 * TILE_B + so, Al + ga);
            CP16(stg + 2 * TILE_B + so, Bh + gb);
            CP16(stg + 3 * TILE_B + so, Bl + gb);
        }
    };

    issue_stage(0, 0);
    CP_COMMIT();

    for (int kt = 0; kt < NT; ++kt) {
        const int s = kt & 1;
        if (kt + 1 < NT) {
            issue_stage(kt + 1, s ^ 1);
            CP_COMMIT();
            CP_WAIT1();
        } else {
            CP_WAIT0();
        }
        __syncthreads();
        const uint32_t stg = smbase + (uint32_t)(s * STAGE_B);
#pragma unroll
        for (int h = 0; h < 2; ++h) {
            const int kk = h << 4;
            uint32_t afh[4][4], afl[4][4], bfh[4][2], bfl[4][2];
#pragma unroll
            for (int mi = 0; mi < 4; ++mi) {
                const uint32_t off = (uint32_t)(((a_row + mi * 16) * SPAD + kk + a_csel) * 2);
                LDSM4(afh[mi][0], afh[mi][1], afh[mi][2], afh[mi][3], stg + 0 * TILE_B + off);
                LDSM4(afl[mi][0], afl[mi][1], afl[mi][2], afl[mi][3], stg + 1 * TILE_B + off);
            }
#pragma unroll
            for (int ni = 0; ni < 4; ++ni) {
                const uint32_t off = (uint32_t)(((b_row + ni * 8) * SPAD + kk + b_csel) * 2);
                LDSM2(bfh[ni][0], bfh[ni][1], stg + 2 * TILE_B + off);
                LDSM2(bfl[ni][0], bfl[ni][1], stg + 3 * TILE_B + off);
            }
#pragma unroll
            for (int mi = 0; mi < 4; ++mi)
#pragma unroll
                for (int ni = 0; ni < 4; ++ni) {
                    float* c4 = acc[mi][ni];
                    MMA16816(c4[0], c4[1], c4[2], c4[3],
                             afh[mi][0], afh[mi][1], afh[mi][2], afh[mi][3],
                             bfh[ni][0], bfh[ni][1]);
                    MMA16816(c4[0], c4[1], c4[2], c4[3],
                             afh[mi][0], afh[mi][1], afh[mi][2], afh[mi][3],
                             bfl[ni][0], bfl[ni][1]);
                    MMA16816(c4[0], c4[1], c4[2], c4[3],
                             afl[mi][0], afl[mi][1], afl[mi][2], afl[mi][3],
                             bfh[ni][0], bfh[ni][1]);
                }
        }
        __syncthreads();
    }

    const int g = lane >> 2, tc = lane & 3;
#pragma unroll
    for (int mi = 0; mi < 4; ++mi) {
#pragma unroll
        for (int ni = 0; ni < 4; ++ni) {
            const int r0 = m0 + wm * 64 + mi * 16 + g;
            const int cc = n0 + wn * 32 + ni * 8 + tc * 2;
            const float bb0 = bias[cc], bb1 = bias[cc + 1];
            store_c(C, r0,     cc, acc[mi][ni][0] + bb0, acc[mi][ni][1] + bb1, M, N, fcmode);
            store_c(C, r0 + 8, cc, acc[mi][ni][2] + bb0, acc[mi][ni][3] + bb1, M, N, fcmode);
        }
    }
}

// encoder [dir][b][512] (bf16 + c fp32) -> decoder [b][1024]
__global__ void concat_hc_kernel(const __nv_bfloat16* __restrict__ hsrc,
                                 const __nv_bfloat16* __restrict__ lsrc,
                                 const float* __restrict__ csrc,
                                 __nv_bfloat16* __restrict__ hdst,
                                 __nv_bfloat16* __restrict__ ldst,
                                 float* __restrict__ cdst) {
    const int idx = blockIdx.x * 256 + threadIdx.x;
    const int b = idx >> 10, col = idx & 1023;
    const int dir = col >> 9, u = col & 511;
    const int s = dir * 8192 + b * 512 + u;
    hdst[idx] = hsrc[s];
    ldst[idx] = lsrc[s];
    cdst[idx] = csrc[s];
}

__global__ void zero_t0_kernel(float* __restrict__ out) {
    const int idx = blockIdx.x * 256 + threadIdx.x;
    if (idx < 16 * VOCAB) {
        const int b = idx / VOCAB, v = idx - b * VOCAB;
        out[(size_t)b * T_LEN * VOCAB + v] = 0.f;
    }
}

// ---------------- driver ----------------
extern "C" void kernel_launch(void* const* d_in, const int* in_sizes, int n_in,
                              void* d_out, int out_size) {
    (void)in_sizes; (void)n_in; (void)out_size;
    const int*   src       = (const int*)d_in[0];
    const int*   tgt       = (const int*)d_in[1];
    const float* enc_embed = (const float*)d_in[3];
    const float* enc_Wih   = (const float*)d_in[4];
    const float* enc_Whh   = (const float*)d_in[5];
    const float* enc_b     = (const float*)d_in[6];
    const float* dec_embed = (const float*)d_in[7];
    const float* dec_Wih   = (const float*)d_in[8];
    const float* dec_Whh   = (const float*)d_in[9];
    const float* dec_b     = (const float*)d_in[10];
    const float* fc_W      = (const float*)d_in[11];
    const float* fc_b      = (const float*)d_in[12];
    float* out = (float*)d_out;

    float *xp, *eC, *c0, *c1;
    __nv_bfloat16 *Ah, *Al, *Wh, *Wl, *WrH, *WrL;
    __nv_bfloat16 *ehbA,*elbA,*ehbB,*elbB;
    __nv_bfloat16 *dhbA,*dlbA,*dhbB,*dlbB,*dhbC,*dlbC,*dhbD,*dlbD;
    cudaGetSymbolAddress((void**)&xp, g_xproj);
    cudaGetSymbolAddress((void**)&eC, g_encC);
    cudaGetSymbolAddress((void**)&c0, g_dc0);
    cudaGetSymbolAddress((void**)&c1, g_dc1);
    cudaGetSymbolAddress((void**)&Ah, g_Ah);
    cudaGetSymbolAddress((void**)&Al, g_Al);
    cudaGetSymbolAddress((void**)&Wh, g_Wh);
    cudaGetSymbolAddress((void**)&Wl, g_Wl);
    cudaGetSymbolAddress((void**)&WrH, g_WrH);
    cudaGetSymbolAddress((void**)&WrL, g_WrL);
    cudaGetSymbolAddress((void**)&ehbA, g_ehbA);
    cudaGetSymbolAddress((void**)&elbA, g_elbA);
    cudaGetSymbolAddress((void**)&ehbB, g_ehbB);
    cudaGetSymbolAddress((void**)&elbB, g_elbB);
    cudaGetSymbolAddress((void**)&dhbA, g_dhbA);
    cudaGetSymbolAddress((void**)&dlbA, g_dlbA);
    cudaGetSymbolAddress((void**)&dhbB, g_dhbB);
    cudaGetSymbolAddress((void**)&dlbB, g_dlbB);
    cudaGetSymbolAddress((void**)&dhbC, g_dhbC);
    cudaGetSymbolAddress((void**)&dlbC, g_dlbC);
    cudaGetSymbolAddress((void**)&dhbD, g_dhbD);
    cudaGetSymbolAddress((void**)&dlbD, g_dlbD);

    const int ENC_SMEM = 2 * 16 * (512 + 8) * 2 + 16 * 16 * 40 * 4;   // 74240
    const int DEC_SMEM = 2 * 16 * (1024 + 8) * 2 + 16 * 16 * 40 * 4;  // 107008
    cudaFuncSetAttribute(lstm_chain_mma<512, 2>,
                         cudaFuncAttributeMaxDynamicSharedMemorySize, ENC_SMEM);
    cudaFuncSetAttribute(lstm_chain_mma<1024, 1>,
                         cudaFuncAttributeMaxDynamicSharedMemorySize, DEC_SMEM);
    cudaFuncSetAttribute(gemm_bf16x3_kernel,
                         cudaFuncAttributeMaxDynamicSharedMemorySize, GEMM_SMEM);

    auto splitN = [](const float* s, __nv_bfloat16* h, __nv_bfloat16* l, int n) {
        int n2 = n >> 1;
        split_kernel<<<(n2 + 255) / 256, 256>>>((const float2*)s,
                                                (__nv_bfloat162*)h, (__nv_bfloat162*)l, n2);
    };

    // ===== Encoder =====
    enc_embed_kernel<<<2048, 256>>>(enc_embed, src, Ah, Al);
    for (int l = 0; l < 2; ++l) {
        cudaMemsetAsync(ehbA, 0, 16384 * sizeof(__nv_bfloat16));
        cudaMemsetAsync(elbA, 0, 16384 * sizeof(__nv_bfloat16));
        cudaMemsetAsync(eC, 0, 16384 * sizeof(float));
        splitN(enc_Wih + (size_t)l * 4096 * 1024, Wh, Wl, 4096 * 1024);
        gemm_bf16x3_kernel<<<dim3(32, 16), 256, GEMM_SMEM>>>(
            Ah, Al, Wh, Wl, enc_b + l * 4096, xp, 2048, 4096, 1024, 0);
        splitN(enc_Whh + (size_t)l * 2 * 2048 * 512, WrH, WrL, 2 * 2048 * 512);
        lstm_chain_mma<512, 2><<<128, 512, ENC_SMEM>>>(
            WrH, WrL, ehbA, elbA, ehbB, elbB, eC, xp,
            (l == 0) ? Ah : nullptr, (l == 0) ? Al : nullptr, 128);
        __nv_bfloat16* hd = (l == 0) ? dhbA : dhbC;
        __nv_bfloat16* ld = (l == 0) ? dlbA : dlbC;
        float* cd = (l == 0) ? c0 : c1;
        concat_hc_kernel<<<64, 256>>>(ehbA, elbA, eC, hd, ld, cd);
    }

    // ===== Decoder =====
    dec_embed_kernel<<<2032, 256>>>(dec_embed, tgt, Ah, Al);
    // layer 0
    splitN(dec_Wih, Wh, Wl, 4096 * 1024);
    gemm_bf16x3_kernel<<<dim3(32, 16), 256, GEMM_SMEM>>>(
        Ah, Al, Wh, Wl, dec_b, xp, 2032, 4096, 1024, 0);
    splitN(dec_Whh, WrH, WrL, 4096 * 1024);
    lstm_chain_mma<1024, 1><<<128, 512, DEC_SMEM>>>(
        WrH, WrL, dhbA, dlbA, dhbB, dlbB, c0, xp, Ah, Al, 127);   // h0seq -> Ah/Al
    // layer 1
    splitN(dec_Wih + (size_t)4096 * 1024, Wh, Wl, 4096 * 1024);
    gemm_bf16x3_kernel<<<dim3(32, 16), 256, GEMM_SMEM>>>(
        Ah, Al, Wh, Wl, dec_b + 4096, xp, 2032, 4096, 1024, 0);
    splitN(dec_Whh + (size_t)4096 * 1024, WrH, WrL, 4096 * 1024);
    lstm_chain_mma<1024, 1><<<128, 512, DEC_SMEM>>>(
        WrH, WrL, dhbC, dlbC, dhbD, dlbD, c1, xp, Ah, Al, 127);   // h1seq -> Ah/Al

    // ===== Output =====
    zero_t0_kernel<<<2000, 256>>>(out);
    splitN(fc_W, Wh, Wl, 32000 * 1024);
    gemm_bf16x3_kernel<<<dim3(250, 16), 256, GEMM_SMEM>>>(
        Ah, Al, Wh, Wl, fc_b, out, 2032, VOCAB, 1024, 1);
}

// round 16
// speedup vs baseline: 1.4129x; 1.0200x over previous
#include <cuda_runtime.h>
#include <cuda_bf16.h>
#include <cstdint>

#define S_LEN 128
#define T_LEN 128
#define BATCH 16
#define VOCAB 32000

// ---------------- static scratch ----------------
__device__ float g_xproj[2048 * 4096];   // x@Wih^T + b (per stage)
__device__ float g_encC[16384];          // encoder c [dir][b][512]
__device__ float g_dc0[16384], g_dc1[16384]; // decoder c per layer
// bf16 hidden-state ping-pongs (hi/lo pairs)
__device__ __nv_bfloat16 g_ehbA[16384], g_elbA[16384];  // encoder [dir][b][512]
__device__ __nv_bfloat16 g_ehbB[16384], g_elbB[16384];
__device__ __nv_bfloat16 g_dhbA[16384], g_dlbA[16384];  // decoder L0 [b][1024]
__device__ __nv_bfloat16 g_dhbB[16384], g_dlbB[16384];
__device__ __nv_bfloat16 g_dhbC[16384], g_dlbC[16384];  // decoder L1
__device__ __nv_bfloat16 g_dhbD[16384], g_dlbD[16384];
// bf16-split buffers
__device__ __nv_bfloat16 g_Ah[2048 * 1024];   // activations hi (GEMM A)
__device__ __nv_bfloat16 g_Al[2048 * 1024];   // activations lo
__device__ __nv_bfloat16 g_Wh[32768 * 1024];  // Wih / fc_W hi
__device__ __nv_bfloat16 g_Wl[32768 * 1024];
// grid barrier state (2 independent barrier ids)
__device__ unsigned g_barc[2] = {0u, 0u};
__device__ unsigned g_barg[2] = {0u, 0u};

// ---------------- grid-wide barrier (participants co-resident) ----------------
__device__ __forceinline__ void grid_barrier(int id, unsigned n) {
    __threadfence();
    __syncthreads();
    if (threadIdx.x == 0) {
        volatile unsigned* vg = &g_barg[id];
        const unsigned gen = *vg;
        if (atomicAdd(&g_barc[id], 1u) == n - 1u) {
            g_barc[id] = 0u;
            __threadfence();
            atomicAdd((unsigned*)vg, 1u);
        } else {
            while (*vg == gen) { }
        }
    }
    __syncthreads();
}

// ---------------- embedding gathers -> bf16 hi/lo ----------------
__device__ __forceinline__ void split4_store(__nv_bfloat16* h, __nv_bfloat16* l,
                                             size_t off, float4 v) {
    __nv_bfloat162 h0 = __floats2bfloat162_rn(v.x, v.y);
    __nv_bfloat162 h1 = __floats2bfloat162_rn(v.z, v.w);
    __nv_bfloat162 l0 = __floats2bfloat162_rn(v.x - __bfloat162float(h0.x),
                                              v.y - __bfloat162float(h0.y));
    __nv_bfloat162 l1 = __floats2bfloat162_rn(v.z - __bfloat162float(h1.x),
                                              v.w - __bfloat162float(h1.y));
    *(__nv_bfloat162*)(h + off) = h0; *(__nv_bfloat162*)(h + off + 2) = h1;
    *(__nv_bfloat162*)(l + off) = l0; *(__nv_bfloat162*)(l + off + 2) = l1;
}

__global__ void enc_embed_kernel(const float* __restrict__ emb,
                                 const int* __restrict__ src,
                                 __nv_bfloat16* __restrict__ xh,
                                 __nv_bfloat16* __restrict__ xl) {
    int r = blockIdx.x, t = r >> 4, b = r & 15;
    int tok = src[b * S_LEN + t];
    float4 v = ((const float4*)(emb + (size_t)tok * 1024))[threadIdx.x];
    split4_store(xh, xl, (size_t)r * 1024 + threadIdx.x * 4, v);
}
__global__ void dec_embed_kernel(const float* __restrict__ emb,
                                 const int* __restrict__ tgt,
                                 __nv_bfloat16* __restrict__ xh,
                                 __nv_bfloat16* __restrict__ xl) {
    int r = blockIdx.x, s = r >> 4, b = r & 15;
    int tok = (s == 0) ? 1 : tgt[b * T_LEN + s];
    float4 v = ((const float4*)(emb + (size_t)tok * 1024))[threadIdx.x];
    split4_store(xh, xl, (size_t)r * 1024 + threadIdx.x * 4, v);
}

// ---------------- fp32 -> (hi, lo) bf16 split (weights), float4 streaming ----
__global__ void split_kernel(const float4* __restrict__ s,
                             uint2* __restrict__ h,
                             uint2* __restrict__ l, int n4) {
    int i = blockIdx.x * 256 + threadIdx.x;
    if (i < n4) {
        float4 v = __ldcs(s + i);
        __nv_bfloat162 h0 = __floats2bfloat162_rn(v.x, v.y);
        __nv_bfloat162 h1 = __floats2bfloat162_rn(v.z, v.w);
        __nv_bfloat162 l0 = __floats2bfloat162_rn(v.x - __bfloat162float(h0.x),
                                                  v.y - __bfloat162float(h0.y));
        __nv_bfloat162 l1 = __floats2bfloat162_rn(v.z - __bfloat162float(h1.x),
                                                  v.w - __bfloat162float(h1.y));
        uint2 hv; hv.x = *(uint32_t*)&h0; hv.y = *(uint32_t*)&h1;
        uint2 lv; lv.x = *(uint32_t*)&l0; lv.y = *(uint32_t*)&l1;
        __stcs(h + i, hv);
        __stcs(l + i, lv);
    }
}

// ---------------- MMA helpers ----------------
#define LDSM4(d0,d1,d2,d3,addr) \
    asm volatile("ldmatrix.sync.aligned.m8n8.x4.shared.b16 {%0,%1,%2,%3}, [%4];" \
                 : "=r"(d0),"=r"(d1),"=r"(d2),"=r"(d3) : "r"(addr))
#define MMA16816(c0,c1,c2,c3,a0,a1,a2,a3,b0,b1) \
    asm volatile("mma.sync.aligned.m16n8k16.row.col.f32.bf16.bf16.f32 " \
                 "{%0,%1,%2,%3},{%4,%5,%6,%7},{%8,%9},{%0,%1,%2,%3};" \
                 : "+f"(c0),"+f"(c1),"+f"(c2),"+f"(c3) \
                 : "r"(a0),"r"(a1),"r"(a2),"r"(a3),"r"(b0),"r"(b1))
#define CP16(dst, src) \
    asm volatile("cp.async.cg.shared.global [%0], [%1], 16;" \
                 :: "r"(dst), "l"(src) : "memory")
#define CP_COMMIT() asm volatile("cp.async.commit_group;" ::: "memory")
#define CP_WAIT1()  asm volatile("cp.async.wait_group 1;" ::: "memory")
#define CP_WAIT0()  asm volatile("cp.async.wait_group 0;" ::: "memory")

// ---------------- persistent LSTM chain on tensor cores ----------------
// 512 threads / 16 warps. Block owns 8 units -> N=32 gate rows.
// Whh loaded fp32 and split to hi/lo bf16 fragments IN REGISTERS once
// (loop-invariant). Per step: h via ldmatrix, 12 reg-resident MMAs,
// smem partial reduce, 128-thread gate epilogue.
template <int U, int NDIR>
__global__ void __launch_bounds__(512, 1)
lstm_chain_mma(const float* __restrict__ Whh,     // [NDIR][4U][U] fp32
               __nv_bfloat16* hbA, __nv_bfloat16* lbA,
               __nv_bfloat16* hbB, __nv_bfloat16* lbB,
               float* __restrict__ c,
               const float* __restrict__ xpbase,   // [nsteps][B][4096]
               __nv_bfloat16* ybh, __nv_bfloat16* ybl,  // optional [nsteps][B][1024]
               int nsteps) {
    extern __shared__ char smraw[];
    __nv_bfloat16* hbs = (__nv_bfloat16*)smraw;        // [16][U+8]
    __nv_bfloat16* lbs = hbs + 16 * (U + 8);
    float* zbuf = (float*)(lbs + 16 * (U + 8));        // [16][16][40]

    const int tid = threadIdx.x, warp = tid >> 5, lane = tid & 31;
    const int dir = (NDIR == 2) ? (blockIdx.x >> 6) : 0;
    const int u0 = ((NDIR == 2) ? (blockIdx.x & 63) : blockIdx.x) * 8;
    const float* Whd = Whh + (size_t)dir * 4 * U * U;

    const uint32_t hb_sb = (uint32_t)__cvta_generic_to_shared(hbs);
    const uint32_t lb_sb = (uint32_t)__cvta_generic_to_shared(lbs);

    const int eb = tid >> 3, eu = tid & 7;   // epilogue (batch, unit-offset), tid<128
    const int uu = u0 + eu;
    const size_t cidx = (size_t)dir * BATCH * U + (size_t)eb * U + uu;
    float cr = (tid < 128) ? c[cidx] : 0.f;

    constexpr int KT = U / 256;              // k-tiles (of 16) per warp
    const int kbase = warp * (U / 16);
    const uint32_t aoff = (uint32_t)(((lane & 15) * (U + 8) + ((lane >> 4) << 3)) * 2);
    const int brow = (lane >> 2);
    const int bk = (lane & 3) << 1;

    // ---- hoist Whh fragments: load fp32, split to hi/lo bf16 in registers ----
    uint32_t Bh[KT][4][2], Bl[KT][4][2];
#pragma unroll
    for (int t = 0; t < KT; ++t) {
        const int kk = kbase + t * 16;
#pragma unroll
        for (int g = 0; g < 4; ++g) {
            const size_t ro = (size_t)(g * U + u0 + brow) * U + kk + bk;
            const float2 w0 = *(const float2*)(Whd + ro);
            const float2 w1 = *(const float2*)(Whd + ro + 8);
            __nv_bfloat162 b0h = __floats2bfloat162_rn(w0.x, w0.y);
            __nv_bfloat162 b1h = __floats2bfloat162_rn(w1.x, w1.y);
            __nv_bfloat162 b0l = __floats2bfloat162_rn(w0.x - __bfloat162float(b0h.x),
                                                       w0.y - __bfloat162float(b0h.y));
            __nv_bfloat162 b1l = __floats2bfloat162_rn(w1.x - __bfloat162float(b1h.x),
                                                       w1.y - __bfloat162float(b1h.y));
            Bh[t][g][0] = *(uint32_t*)&b0h;  Bh[t][g][1] = *(uint32_t*)&b1h;
            Bl[t][g][0] = *(uint32_t*)&b0l;  Bl[t][g][1] = *(uint32_t*)&b1l;
        }
    }

    const int barid = (NDIR == 2) ? dir : 0;
    const unsigned barn = (NDIR == 2) ? 64u : 128u;

    for (int j = 0; j < nsteps; ++j) {
        const __nv_bfloat16* hin_h = (j & 1) ? hbB : hbA;
        const __nv_bfloat16* hin_l = (j & 1) ? lbB : lbA;
        __nv_bfloat16* hout_h = (j & 1) ? hbA : hbB;
        __nv_bfloat16* hout_l = (j & 1) ? lbA : lbB;

        // xp prefetch (epilogue threads only)
        float xpi = 0.f, xpf = 0.f, xpg = 0.f, xpo = 0.f;
        size_t yoff = 0;
        if (tid < 128) {
            const float* xp;
            if (NDIR == 2 && dir == 1) {
                const int jr = nsteps - 1 - j;
                xp = xpbase + (size_t)jr * 65536 + 2048 + (size_t)eb * 4096;
                yoff = (size_t)jr * 16384 + (size_t)eb * 1024 + 512 + uu;
            } else {
                xp = xpbase + (size_t)j * 65536 + (size_t)eb * 4096;
                yoff = (size_t)j * 16384 + (size_t)eb * 1024 + uu;
            }
            xpi = __ldg(xp + 0 * U + uu);
            xpf = __ldg(xp + 1 * U + uu);
            xpg = __ldg(xp + 2 * U + uu);
            xpo = __ldg(xp + 3 * U + uu);
        }

        // load h (bf16 hi/lo) into padded smem, L1-bypassed
        {
            const uint4* s4h = (const uint4*)(hin_h + (size_t)dir * 16 * U);
            const uint4* s4l = (const uint4*)(hin_l + (size_t)dir * 16 * U);
            constexpr int C8 = U / 8;
            for (int i = tid; i < 16 * C8; i += 512) {
                const int row = i / C8, c8 = i - row * C8;
                *(uint4*)(hbs + row * (U + 8) + c8 * 8) = __ldcg(s4h + i);
                *(uint4*)(lbs + row * (U + 8) + c8 * 8) = __ldcg(s4l + i);
            }
        }
        __syncthreads();

        float acc[4][4];
#pragma unroll
        for (int g = 0; g < 4; ++g)
#pragma unroll
            for (int q = 0; q < 4; ++q) acc[g][q] = 0.f;

#pragma unroll
        for (int t = 0; t < KT; ++t) {
            const int kk = kbase + t * 16;
            uint32_t ah0, ah1, ah2, ah3, al0, al1, al2, al3;
            LDSM4(ah0, ah1, ah2, ah3, hb_sb + aoff + kk * 2);
            LDSM4(al0, al1, al2, al3, lb_sb + aoff + kk * 2);
#pragma unroll
            for (int g = 0; g < 4; ++g) {
                MMA16816(acc[g][0], acc[g][1], acc[g][2], acc[g][3],
                         ah0, ah1, ah2, ah3, Bh[t][g][0], Bh[t][g][1]);
                MMA16816(acc[g][0], acc[g][1], acc[g][2], acc[g][3],
                         ah0, ah1, ah2, ah3, Bl[t][g][0], Bl[t][g][1]);
                MMA16816(acc[g][0], acc[g][1], acc[g][2], acc[g][3],
                         al0, al1, al2, al3, Bh[t][g][0], Bh[t][g][1]);
            }
        }
        // store partial z: zbuf[warp][b][n], row stride 40 (bank-spread)
        {
            const int r0 = lane >> 2;
#pragma unroll
            for (int g = 0; g < 4; ++g) {
                const int n = g * 8 + bk;
                float2 v01; v01.x = acc[g][0]; v01.y = acc[g][1];
                float2 v23; v23.x = acc[g][2]; v23.y = acc[g][3];
                *(float2*)(zbuf + (warp * 16 + r0) * 40 + n) = v01;
                *(float2*)(zbuf + (warp * 16 + r0 + 8) * 40 + n) = v23;
            }
        }
        __syncthreads();

        if (tid < 128) {
            float z0 = xpi, z1 = xpf, z2 = xpg, z3 = xpo;
#pragma unroll
            for (int s = 0; s < 16; ++s) {
                const float* zr = zbuf + (s * 16 + eb) * 40;
                z0 += zr[0 * 8 + eu];
                z1 += zr[1 * 8 + eu];
                z2 += zr[2 * 8 + eu];
                z3 += zr[3 * 8 + eu];
            }
            const float ig = 1.f / (1.f + __expf(-z0));
            const float fg = 1.f / (1.f + __expf(-z1));
            const float gg = tanhf(z2);
            const float og = 1.f / (1.f + __expf(-z3));
            const float cn = fg * cr + ig * gg;
            cr = cn;
            const float hn = og * tanhf(cn);
            const __nv_bfloat16 hh = __float2bfloat16(hn);
            const __nv_bfloat16 hl = __float2bfloat16(hn - __bfloat162float(hh));
            const size_t ho = (size_t)dir * 16 * U + (size_t)eb * U + uu;
            hout_h[ho] = hh; hout_l[ho] = hl;
            if (ybh) { ybh[yoff] = hh; ybl[yoff] = hl; }
        }
        if (j + 1 < nsteps) grid_barrier(barid, barn);
    }
    if (tid < 128) c[cidx] = cr;
}

// ---------------- bf16-split NT GEMM (cp.async double-buffered) ----------------
#define SPAD 40
#define TILE_B (128 * SPAD * 2)
#define STAGE_B (4 * TILE_B)
#define GEMM_SMEM (2 * STAGE_B)

__device__ __forceinline__ void store_c(float* __restrict__ C, int m, int cc,
                                        float v0, float v1, int M, int N, int fcmode) {
    if (m >= M) return;
    float2 v; v.x = v0; v.y = v1;
    if (fcmode) {
        const int b = m & 15, t = (m >> 4) + 1;
        *(float2*)&C[(size_t)b * T_LEN * VOCAB + (size_t)t * VOCAB + cc] = v;
    } else {
        *(float2*)&C[(size_t)m * N + cc] = v;
    }
}

__global__ void __launch_bounds__(256, 2)
gemm_bf16x3_kernel(const __nv_bfloat16* __restrict__ Ah, const __nv_bfloat16* __restrict__ Al,
                   const __nv_bfloat16* __restrict__ Bh, const __nv_bfloat16* __restrict__ Bl,
                   const float* __restrict__ bias, float* __restrict__ C,
                   int M, int N, int K, int fcmode) {
    extern __shared__ __nv_bfloat16 sm[];
    const int tid = threadIdx.x, warp = tid >> 5, lane = tid & 31;
    const int wm = warp >> 2, wn = warp & 3;
    const int m0 = blockIdx.y * 128, n0 = blockIdx.x * 128;
    const int lrow = tid >> 2;
    const int lcol = (tid & 3) << 3;
    const uint32_t smbase = (uint32_t)__cvta_generic_to_shared(sm);

    float acc[4][4][4];
#pragma unroll
    for (int i = 0; i < 4; ++i)
#pragma unroll
        for (int j = 0; j < 4; ++j)
#pragma unroll
            for (int q = 0; q < 4; ++q) acc[i][j][q] = 0.f;

    const int a_row = wm * 64 + (lane & 15);
    const int a_csel = (lane >> 4) << 3;
    // B via ldmatrix.x4: lanes 0-15 -> n-rows 0-7 (k-lo/k-hi), 16-31 -> n-rows 8-15
    const int b_row4 = wn * 32 + ((lane >> 4) << 3) + (lane & 7);
    const int b_k4 = lane & 8;
    const int NT = K >> 5;

    auto issue_stage = [&](int kt, int s) {
        const int kc = kt << 5;
        const uint32_t stg = smbase + (uint32_t)(s * STAGE_B);
#pragma unroll
        for (int i = 0; i < 2; ++i) {
            const int r = lrow + i * 64;
            const size_t ga = (size_t)(m0 + r) * K + kc + lcol;
            const size_t gb = (size_t)(n0 + r) * K + kc + lcol;
            const uint32_t so = (uint32_t)(r * SPAD + lcol) * 2;
            CP16(stg + 0 * TILE_B + so, Ah + ga);
            CP16(stg + 1 * TILE_B + so, Al + ga);
            CP16(stg + 2 * TILE_B + so, Bh + gb);
            CP16(stg + 3 * TILE_B + so, Bl + gb);
        }
    };

    issue_stage(0, 0);
    CP_COMMIT();

    for (int kt = 0; kt < NT; ++kt) {
        const int s = kt & 1;
        if (kt + 1 < NT) {
            issue_stage(kt + 1, s ^ 1);
            CP_COMMIT();
            CP_WAIT1();
        } else {
            CP_WAIT0();
        }
        __syncthreads();
        const uint32_t stg = smbase + (uint32_t)(s * STAGE_B);
#pragma unroll
        for (int h = 0; h < 2; ++h) {
            const int kk = h << 4;
            uint32_t afh[4][4], afl[4][4], bfh[4][2], bfl[4][2];
#pragma unroll
            for (int mi = 0; mi < 4; ++mi) {
                const uint32_t off = (uint32_t)(((a_row + mi * 16) * SPAD + kk + a_csel) * 2);
                LDSM4(afh[mi][0], afh[mi][1], afh[mi][2], afh[mi][3], stg + 0 * TILE_B + off);
                LDSM4(afl[mi][0], afl[mi][1], afl[mi][2], afl[mi][3], stg + 1 * TILE_B + off);
            }
#pragma unroll
            for (int p = 0; p < 2; ++p) {
                const uint32_t off = (uint32_t)(((b_row4 + p * 16) * SPAD + kk + b_k4) * 2);
                LDSM4(bfh[2*p][0], bfh[2*p][1], bfh[2*p+1][0], bfh[2*p+1][1],
                      stg + 2 * TILE_B + off);
                LDSM4(bfl[2*p][0], bfl[2*p][1], bfl[2*p+1][0], bfl[2*p+1][1],
                      stg + 3 * TILE_B + off);
            }
#pragma unroll
            for (int mi = 0; mi < 4; ++mi)
#pragma unroll
                for (int ni = 0; ni < 4; ++ni) {
                    float* c4 = acc[mi][ni];
                    MMA16816(c4[0], c4[1], c4[2], c4[3],
                             afh[mi][0], afh[mi][1], afh[mi][2], afh[mi][3],
                             bfh[ni][0], bfh[ni][1]);
                    MMA16816(c4[0], c4[1], c4[2], c4[3],
                             afh[mi][0], afh[mi][1], afh[mi][2], afh[mi][3],
                             bfl[ni][0], bfl[ni][1]);
                    MMA16816(c4[0], c4[1], c4[2], c4[3],
                             afl[mi][0], afl[mi][1], afl[mi][2], afl[mi][3],
                             bfh[ni][0], bfh[ni][1]);
                }
        }
        __syncthreads();
    }

    const int g = lane >> 2, tc = lane & 3;
#pragma unroll
    for (int mi = 0; mi < 4; ++mi) {
#pragma unroll
        for (int ni = 0; ni < 4; ++ni) {
            const int r0 = m0 + wm * 64 + mi * 16 + g;
            const int cc = n0 + wn * 32 + ni * 8 + tc * 2;
            const float bb0 = bias[cc], bb1 = bias[cc + 1];
            store_c(C, r0,     cc, acc[mi][ni][0] + bb0, acc[mi][ni][1] + bb1, M, N, fcmode);
            store_c(C, r0 + 8, cc, acc[mi][ni][2] + bb0, acc[mi][ni][3] + bb1, M, N, fcmode);
        }
    }
}

// encoder [dir][b][512] (bf16 + c fp32) -> decoder [b][1024]
__global__ void concat_hc_kernel(const __nv_bfloat16* __restrict__ hsrc,
                                 const __nv_bfloat16* __restrict__ lsrc,
                                 const float* __restrict__ csrc,
                                 __nv_bfloat16* __restrict__ hdst,
                                 __nv_bfloat16* __restrict__ ldst,
                                 float* __restrict__ cdst) {
    const int idx = blockIdx.x * 256 + threadIdx.x;
    const int b = idx >> 10, col = idx & 1023;
    const int dir = col >> 9, u = col & 511;
    const int s = dir * 8192 + b * 512 + u;
    hdst[idx] = hsrc[s];
    ldst[idx] = lsrc[s];
    cdst[idx] = csrc[s];
}

__global__ void zero_t0_kernel(float* __restrict__ out) {
    const int idx = blockIdx.x * 256 + threadIdx.x;
    if (idx < 16 * VOCAB) {
        const int b = idx / VOCAB, v = idx - b * VOCAB;
        out[(size_t)b * T_LEN * VOCAB + v] = 0.f;
    }
}

// ---------------- driver ----------------
extern "C" void kernel_launch(void* const* d_in, const int* in_sizes, int n_in,
                              void* d_out, int out_size) {
    (void)in_sizes; (void)n_in; (void)out_size;
    const int*   src       = (const int*)d_in[0];
    const int*   tgt       = (const int*)d_in[1];
    const float* enc_embed = (const float*)d_in[3];
    const float* enc_Wih   = (const float*)d_in[4];
    const float* enc_Whh   = (const float*)d_in[5];
    const float* enc_b     = (const float*)d_in[6];
    const float* dec_embed = (const float*)d_in[7];
    const float* dec_Wih   = (const float*)d_in[8];
    const float* dec_Whh   = (const float*)d_in[9];
    const float* dec_b     = (const float*)d_in[10];
    const float* fc_W      = (const float*)d_in[11];
    const float* fc_b      = (const float*)d_in[12];
    float* out = (float*)d_out;

    float *xp, *eC, *c0, *c1;
    __nv_bfloat16 *Ah, *Al, *Wh, *Wl;
    __nv_bfloat16 *ehbA,*elbA,*ehbB,*elbB;
    __nv_bfloat16 *dhbA,*dlbA,*dhbB,*dlbB,*dhbC,*dlbC,*dhbD,*dlbD;
    cudaGetSymbolAddress((void**)&xp, g_xproj);
    cudaGetSymbolAddress((void**)&eC, g_encC);
    cudaGetSymbolAddress((void**)&c0, g_dc0);
    cudaGetSymbolAddress((void**)&c1, g_dc1);
    cudaGetSymbolAddress((void**)&Ah, g_Ah);
    cudaGetSymbolAddress((void**)&Al, g_Al);
    cudaGetSymbolAddress((void**)&Wh, g_Wh);
    cudaGetSymbolAddress((void**)&Wl, g_Wl);
    cudaGetSymbolAddress((void**)&ehbA, g_ehbA);
    cudaGetSymbolAddress((void**)&elbA, g_elbA);
    cudaGetSymbolAddress((void**)&ehbB, g_ehbB);
    cudaGetSymbolAddress((void**)&elbB, g_elbB);
    cudaGetSymbolAddress((void**)&dhbA, g_dhbA);
    cudaGetSymbolAddress((void**)&dlbA, g_dlbA);
    cudaGetSymbolAddress((void**)&dhbB, g_dhbB);
    cudaGetSymbolAddress((void**)&dlbB, g_dlbB);
    cudaGetSymbolAddress((void**)&dhbC, g_dhbC);
    cudaGetSymbolAddress((void**)&dlbC, g_dlbC);
    cudaGetSymbolAddress((void**)&dhbD, g_dhbD);
    cudaGetSymbolAddress((void**)&dlbD, g_dlbD);

    const int ENC_SMEM = 2 * 16 * (512 + 8) * 2 + 16 * 16 * 40 * 4;   // 74240
    const int DEC_SMEM = 2 * 16 * (1024 + 8) * 2 + 16 * 16 * 40 * 4;  // 107008
    cudaFuncSetAttribute(lstm_chain_mma<512, 2>,
                         cudaFuncAttributeMaxDynamicSharedMemorySize, ENC_SMEM);
    cudaFuncSetAttribute(lstm_chain_mma<1024, 1>,
                         cudaFuncAttributeMaxDynamicSharedMemorySize, DEC_SMEM);
    cudaFuncSetAttribute(gemm_bf16x3_kernel,
                         cudaFuncAttributeMaxDynamicSharedMemorySize, GEMM_SMEM);

    auto splitN = [](const float* s, __nv_bfloat16* h, __nv_bfloat16* l, int n) {
        int n4 = n >> 2;
        split_kernel<<<(n4 + 255) / 256, 256>>>((const float4*)s,
                                                (uint2*)h, (uint2*)l, n4);
    };

    // ===== Encoder =====
    enc_embed_kernel<<<2048, 256>>>(enc_embed, src, Ah, Al);
    for (int l = 0; l < 2; ++l) {
        cudaMemsetAsync(ehbA, 0, 16384 * sizeof(__nv_bfloat16));
        cudaMemsetAsync(elbA, 0, 16384 * sizeof(__nv_bfloat16));
        cudaMemsetAsync(eC, 0, 16384 * sizeof(float));
        splitN(enc_Wih + (size_t)l * 4096 * 1024, Wh, Wl, 4096 * 1024);
        gemm_bf16x3_kernel<<<dim3(32, 16), 256, GEMM_SMEM>>>(
            Ah, Al, Wh, Wl, enc_b + l * 4096, xp, 2048, 4096, 1024, 0);
        lstm_chain_mma<512, 2><<<128, 512, ENC_SMEM>>>(
            enc_Whh + (size_t)l * 2 * 2048 * 512,
            ehbA, elbA, ehbB, elbB, eC, xp,
            (l == 0) ? Ah : nullptr, (l == 0) ? Al : nullptr, 128);
        __nv_bfloat16* hd = (l == 0) ? dhbA : dhbC;
        __nv_bfloat16* ld = (l == 0) ? dlbA : dlbC;
        float* cd = (l == 0) ? c0 : c1;
        concat_hc_kernel<<<64, 256>>>(ehbA, elbA, eC, hd, ld, cd);
    }

    // ===== Decoder =====
    dec_embed_kernel<<<2032, 256>>>(dec_embed, tgt, Ah, Al);
    // layer 0
    splitN(dec_Wih, Wh, Wl, 4096 * 1024);
    gemm_bf16x3_kernel<<<dim3(32, 16), 256, GEMM_SMEM>>>(
        Ah, Al, Wh, Wl, dec_b, xp, 2032, 4096, 1024, 0);
    lstm_chain_mma<1024, 1><<<128, 512, DEC_SMEM>>>(
        dec_Whh, dhbA, dlbA, dhbB, dlbB, c0, xp, Ah, Al, 127);   // h0seq -> Ah/Al
    // layer 1
    splitN(dec_Wih + (size_t)4096 * 1024, Wh, Wl, 4096 * 1024);
    gemm_bf16x3_kernel<<<dim3(32, 16), 256, GEMM_SMEM>>>(
        Ah, Al, Wh, Wl, dec_b + 4096, xp, 2032, 4096, 1024, 0);
    lstm_chain_mma<1024, 1><<<128, 512, DEC_SMEM>>>(
        dec_Whh + (size_t)4096 * 1024, dhbC, dlbC, dhbD, dlbD, c1, xp, Ah, Al, 127);

    // ===== Output =====
    zero_t0_kernel<<<2000, 256>>>(out);
    splitN(fc_W, Wh, Wl, 32000 * 1024);
    gemm_bf16x3_kernel<<<dim3(250, 16), 256, GEMM_SMEM>>>(
        Ah, Al, Wh, Wl, fc_b, out, 2032, VOCAB, 1024, 1);
}